// round 9
// baseline (speedup 1.0000x reference)
#include <cuda_runtime.h>
#include <cstdint>

#define B_   4
#define C_   256
#define H_   128
#define W_   128
#define Q_   100
#define OUT_ 7
#define BINS (OUT_ * OUT_)   // 49

#define YT_  4               // rows per y-tile
#define NT_  (H_ / YT_)      // 32 y-tiles

// SAT, tile-local y-scan, channel-last: S[b][y][x][c], 64 MB.
__device__ float g_sat[(size_t)B_ * H_ * W_ * C_];
// Exclusive tile-prefix: off[b][t][x][c], 16 MB.
// Tile 0 is NEVER written: device globals are zero-initialized and K2
// writes only t >= 1, so off[b][0][*][*] == 0 always. K3 uses that region
// both as the t=0 offset AND as a zero-redirect target for invalid corners.
__device__ float g_off[(size_t)B_ * NT_ * W_ * C_];

// per-channel smem offset; conflict-free in BOTH K1 phases
__device__ __forceinline__ int cloff(int cl) { return cl * 520 + (cl >> 2) * 8; }

// ---------------------------------------------------------------------------
// K1: fused x-scan + 4-row tile y-scan + transpose to channel-last.
// Block = (b, yt4, cg of 16 ch). 256 threads = 8 warps; warp owns channels
// {warp, warp+8}. All 8 row-loads up front (MLP=8). One barrier.
// launch_bounds(256,5): cap regs ~51 -> 5 blocks/SM (smem 33KB*5=165<228).
// ---------------------------------------------------------------------------
__global__ __launch_bounds__(256, 5) void k1_fused(const float* __restrict__ x,
                                                   float* __restrict__ S) {
    const int bx = blockIdx.x;
    const int cg = bx & 15;                   // 16 groups of 16 channels
    const int yt = (bx >> 4) & (NT_ - 1);     // 0..31
    const int b  = bx >> 9;                   // 0..3

    const int tid  = threadIdx.x;
    const int lane = tid & 31;
    const int warp = tid >> 5;                // 0..7

    __shared__ __align__(16) float s[16 * 520 + 32];
    float4* s4 = reinterpret_cast<float4*>(s);

    const float4* src0 = reinterpret_cast<const float4*>(
        x + ((size_t)(b * C_ + cg * 16 + warp) * H_ + yt * YT_) * W_);
    const float4* src1 = src0 + (size_t)8 * H_ * W_ / 4;   // channel +8

    float4 v0[YT_], v1[YT_];
    #pragma unroll
    for (int r = 0; r < YT_; r++) v0[r] = src0[r * 32 + lane];
    #pragma unroll
    for (int r = 0; r < YT_; r++) v1[r] = src1[r * 32 + lane];

    #pragma unroll
    for (int k = 0; k < 2; k++) {
        const int cl = warp + 8 * k;
        float4* vv = k ? v1 : v0;
        float4 acc = make_float4(0.f, 0.f, 0.f, 0.f);
        const int sb = cloff(cl) / 4;
        #pragma unroll
        for (int yy = 0; yy < YT_; yy++) {
            float4 w = vv[yy];
            w.y += w.x; w.z += w.y; w.w += w.z;
            float sum = w.w;
            #pragma unroll
            for (int off = 1; off < 32; off <<= 1) {
                float t = __shfl_up_sync(0xffffffffu, sum, off);
                if (lane >= off) sum += t;
            }
            const float pre = sum - w.w;
            acc.x += w.x + pre;
            acc.y += w.y + pre;
            acc.z += w.z + pre;
            acc.w += w.w + pre;
            s4[sb + yy * 32 + lane] = acc;
        }
    }
    __syncthreads();

    // write-out: 2048 float4; f = ((yy*128 + xx)*4 + cq)
    float4* S4 = reinterpret_cast<float4*>(S);
    const size_t obase = ((size_t)(b * H_ + yt * YT_)) * (W_ * C_ / 4) + cg * 4;
    #pragma unroll
    for (int it = 0; it < 8; it++) {
        const int f  = it * 256 + tid;
        const int cq = f & 3;
        const int xx = (f >> 2) & 127;
        const int yy = f >> 9;
        float4 o;
        o.x = s[cloff(4 * cq + 0) + yy * 128 + xx];
        o.y = s[cloff(4 * cq + 1) + yy * 128 + xx];
        o.z = s[cloff(4 * cq + 2) + yy * 128 + xx];
        o.w = s[cloff(4 * cq + 3) + yy * 128 + xx];
        S4[obase + ((size_t)yy * W_ + xx) * (C_ / 4) + cq] = o;
    }
}

// ---------------------------------------------------------------------------
// K2: exclusive tile prefix (float4). Tile column-sum == SAT row y = t*4+3.
// Tile 0 never written (stays zero).
// ---------------------------------------------------------------------------
__global__ __launch_bounds__(256) void k2_tilescan(const float4* __restrict__ S4,
                                                   float4* __restrict__ off4) {
    const int g   = blockIdx.x * 256 + threadIdx.x;   // 0 .. B*8192-1
    const int b   = g >> 13;
    const int rem = g & 8191;
    const float4* Sb = S4 + (size_t)b * (H_ * W_ * C_ / 4);
    float4* Ob = off4 + (size_t)b * (NT_ * W_ * C_ / 4);

    float4 acc = Sb[(size_t)3 * 8192 + rem];
    #pragma unroll
    for (int t = 1; t < NT_; t++) {
        Ob[(size_t)t * 8192 + rem] = acc;
        if (t < NT_ - 1) {
            const float4 v = Sb[(size_t)(t * YT_ + 3) * 8192 + rem];
            acc.x += v.x; acc.y += v.y; acc.z += v.z; acc.w += v.w;
        }
    }
}

// ---------------------------------------------------------------------------
// K3: gather. Grid = (B*Q, 4 cgroups of 64 ch). 256 thr = 16 ch-quads x
// 16 bin stripes; 3 bins/thread, 24 UNCONDITIONAL loads (invalid corners
// redirected to the guaranteed-zero off[b][0][0] region) -> max batching.
// ---------------------------------------------------------------------------
__global__ __launch_bounds__(256) void k3_gather(const int* __restrict__ rois,
                                                 const float* __restrict__ S,
                                                 const float* __restrict__ off,
                                                 float* __restrict__ out) {
    const int bq = blockIdx.x;           // 0 .. B*Q-1
    const int cg = blockIdx.y;           // 0..3 (64 channels)
    const int b  = bq / Q_;
    const int tid = threadIdx.x;

    __shared__ int   e_ys[OUT_], e_ye[OUT_], e_xs[OUT_], e_xe[OUT_];
    __shared__ float ia[BINS];
    __shared__ float stage[64 * 51];

    const int* r = rois + bq * 5;        // [bidx, x1, y1, x2, y2]

    if (tid < OUT_) {
        int y1 = r[2], leny = r[4] - r[2];
        e_ys[tid] = y1 + (tid * leny) / OUT_;
        e_ye[tid] = y1 + ((tid + 1) * leny + (OUT_ - 1)) / OUT_;
    } else if (tid < 2 * OUT_) {
        int k = tid - OUT_;
        int x1 = r[1], lenx = r[3] - r[1];
        e_xs[k] = x1 + (k * lenx) / OUT_;
        e_xe[k] = x1 + ((k + 1) * lenx + (OUT_ - 1)) / OUT_;
    }
    __syncthreads();
    if (tid < BINS) {
        int oy = tid / OUT_, ox = tid % OUT_;
        ia[tid] = 1.0f / (float)((e_ye[oy] - e_ys[oy]) * (e_xe[ox] - e_xs[ox]));
    }
    __syncthreads();

    const int lane16 = tid & 15;
    const int sub    = tid >> 4;         // 0..15
    const int c4     = cg * 16 + lane16;

    const float4* Sb4 = reinterpret_cast<const float4*>(S)
                      + (size_t)b * (H_ * W_ * C_ / 4);
    const float4* Ob4 = reinterpret_cast<const float4*>(off)
                      + (size_t)b * (NT_ * W_ * C_ / 4);
    const float4* Z4  = Ob4 + c4;        // guaranteed zero (t=0 region)

    auto evalbin = [&](int bin) -> float4 {
        const int oy = bin / OUT_, ox = bin % OUT_;
        const int ye = e_ye[oy] - 1, xe = e_xe[ox] - 1;   // always >= 0
        const int ys = e_ys[oy] - 1, xs = e_xs[ox] - 1;   // may be -1
        const bool hy = (ys >= 0), hx = (xs >= 0);
        const int ysc = hy ? ys : 0, xsc = hx ? xs : 0;

        const size_t rE  = (size_t)ye * W_;
        const size_t rS  = (size_t)ysc * W_;
        const size_t tE  = (size_t)(ye >> 2) * W_;
        const size_t tS  = (size_t)(ysc >> 2) * W_;

        const float4* p_ee = Sb4 + (rE + xe) * 64 + c4;
        const float4* p_se = hy ? Sb4 + (rS + xe) * 64 + c4 : Z4;
        const float4* p_es = hx ? Sb4 + (rE + xsc) * 64 + c4 : Z4;
        const float4* p_ss = (hy && hx) ? Sb4 + (rS + xsc) * 64 + c4 : Z4;
        const float4* q_ee = Ob4 + (tE + xe) * 64 + c4;
        const float4* q_se = hy ? Ob4 + (tS + xe) * 64 + c4 : Z4;
        const float4* q_es = hx ? Ob4 + (tE + xsc) * 64 + c4 : Z4;
        const float4* q_ss = (hy && hx) ? Ob4 + (tS + xsc) * 64 + c4 : Z4;

        const float4 A = *p_ee, Bv = *p_se, Cv = *p_es, Dv = *p_ss;
        const float4 E = *q_ee, F  = *q_se, G  = *q_es, Hv = *q_ss;
        const float sc = ia[bin];

        return make_float4(
            (A.x - Bv.x - Cv.x + Dv.x + E.x - F.x - G.x + Hv.x) * sc,
            (A.y - Bv.y - Cv.y + Dv.y + E.y - F.y - G.y + Hv.y) * sc,
            (A.z - Bv.z - Cv.z + Dv.z + E.z - F.z - G.z + Hv.z) * sc,
            (A.w - Bv.w - Cv.w + Dv.w + E.w - F.w - G.w + Hv.w) * sc);
    };

    auto stput = [&](int bin, float4 v) {
        const int row = lane16 * 4;
        stage[(row + 0) * 51 + bin] = v.x;
        stage[(row + 1) * 51 + bin] = v.y;
        stage[(row + 2) * 51 + bin] = v.z;
        stage[(row + 3) * 51 + bin] = v.w;
    };

    const float4 r0 = evalbin(sub);
    const float4 r1 = evalbin(sub + 16);
    const float4 r2 = evalbin(sub + 32);
    stput(sub,      r0);
    stput(sub + 16, r1);
    stput(sub + 32, r2);
    if (sub == 0) stput(48, evalbin(48));
    __syncthreads();

    // contiguous slab: out[(bq*256 + cg*64 + ch)*49 + bin], 3136 floats
    float* ob = out + ((size_t)bq * C_ + cg * 64) * BINS;
    #pragma unroll
    for (int i = tid; i < 64 * BINS; i += 256) {
        ob[i] = stage[(i / BINS) * 51 + (i % BINS)];
    }
}

// ---------------------------------------------------------------------------
extern "C" void kernel_launch(void* const* d_in, const int* in_sizes, int n_in,
                              void* d_out, int out_size) {
    const float* x    = (const float*)d_in[0];
    const int*   rois = (const int*)d_in[1];
    float*       out  = (float*)d_out;

    float *sat, *off;
    cudaGetSymbolAddress((void**)&sat, g_sat);
    cudaGetSymbolAddress((void**)&off, g_off);

    k1_fused<<<B_ * NT_ * 16, 256>>>(x, sat);

    k2_tilescan<<<(B_ * 8192) / 256, 256>>>((const float4*)sat, (float4*)off);

    dim3 g3(B_ * Q_, 4);
    k3_gather<<<g3, 256>>>(rois, sat, off, out);
}

// round 10
// speedup vs baseline: 1.1372x; 1.1372x over previous
#include <cuda_runtime.h>
#include <cstdint>

#define B_   4
#define C_   256
#define H_   128
#define W_   128
#define Q_   100
#define OUT_ 7
#define BINS (OUT_ * OUT_)   // 49

#define YT_  4               // rows per y-tile
#define NT_  (H_ / YT_)      // 32 y-tiles

// SAT, tile-local y-scan, channel-last: S[b][y][x][c], 64 MB.
__device__ float g_sat[(size_t)B_ * H_ * W_ * C_];
// Exclusive tile-prefix: off[b][t][x][c], 16 MB.
// Tile 0 is NEVER written: device globals are zero-initialized and K2
// writes only t >= 1, so off[b][0][*][*] == 0 always.
__device__ float g_off[(size_t)B_ * NT_ * W_ * C_];

// per-channel smem offset; conflict-free in BOTH K1 phases
__device__ __forceinline__ int cloff(int cl) { return cl * 520 + (cl >> 2) * 8; }

__device__ __forceinline__ float4 ldcs4(const float4* p) {
    return __ldcs(p);          // evict-first: x is single-use
}

// ---------------------------------------------------------------------------
// K1: fused x-scan + 4-row tile y-scan + transpose to channel-last.
// Block = (b, yt4, cg of 16 ch). 256 threads = 8 warps; warp owns channels
// {warp, warp+8}. All 8 row-loads up front (MLP=8). One barrier.
// (R8 config: launch_bounds(256,4), 62 regs — fastest measured.)
// ---------------------------------------------------------------------------
__global__ __launch_bounds__(256, 4) void k1_fused(const float* __restrict__ x,
                                                   float* __restrict__ S) {
    const int bx = blockIdx.x;
    const int cg = bx & 15;                   // 16 groups of 16 channels
    const int yt = (bx >> 4) & (NT_ - 1);     // 0..31
    const int b  = bx >> 9;                   // 0..3

    const int tid  = threadIdx.x;
    const int lane = tid & 31;
    const int warp = tid >> 5;                // 0..7

    __shared__ __align__(16) float s[16 * 520 + 32];
    float4* s4 = reinterpret_cast<float4*>(s);

    const float4* src0 = reinterpret_cast<const float4*>(
        x + ((size_t)(b * C_ + cg * 16 + warp) * H_ + yt * YT_) * W_);
    const float4* src1 = src0 + (size_t)8 * H_ * W_ / 4;   // channel +8

    float4 v0[YT_], v1[YT_];
    #pragma unroll
    for (int r = 0; r < YT_; r++) v0[r] = ldcs4(src0 + r * 32 + lane);
    #pragma unroll
    for (int r = 0; r < YT_; r++) v1[r] = ldcs4(src1 + r * 32 + lane);

    #pragma unroll
    for (int k = 0; k < 2; k++) {
        const int cl = warp + 8 * k;
        float4* vv = k ? v1 : v0;
        float4 acc = make_float4(0.f, 0.f, 0.f, 0.f);
        const int sb = cloff(cl) / 4;
        #pragma unroll
        for (int yy = 0; yy < YT_; yy++) {
            float4 w = vv[yy];
            w.y += w.x; w.z += w.y; w.w += w.z;
            float sum = w.w;
            #pragma unroll
            for (int off = 1; off < 32; off <<= 1) {
                float t = __shfl_up_sync(0xffffffffu, sum, off);
                if (lane >= off) sum += t;
            }
            const float pre = sum - w.w;
            acc.x += w.x + pre;
            acc.y += w.y + pre;
            acc.z += w.z + pre;
            acc.w += w.w + pre;
            s4[sb + yy * 32 + lane] = acc;
        }
    }
    __syncthreads();

    // write-out: 2048 float4; f = ((yy*128 + xx)*4 + cq)
    float4* S4 = reinterpret_cast<float4*>(S);
    const size_t obase = ((size_t)(b * H_ + yt * YT_)) * (W_ * C_ / 4) + cg * 4;
    #pragma unroll
    for (int it = 0; it < 8; it++) {
        const int f  = it * 256 + tid;
        const int cq = f & 3;
        const int xx = (f >> 2) & 127;
        const int yy = f >> 9;
        float4 o;
        o.x = s[cloff(4 * cq + 0) + yy * 128 + xx];
        o.y = s[cloff(4 * cq + 1) + yy * 128 + xx];
        o.z = s[cloff(4 * cq + 2) + yy * 128 + xx];
        o.w = s[cloff(4 * cq + 3) + yy * 128 + xx];
        S4[obase + ((size_t)yy * W_ + xx) * (C_ / 4) + cq] = o;
    }
}

// ---------------------------------------------------------------------------
// K2: exclusive tile prefix (float4). Tile column-sum == SAT row y = t*4+3.
// Tile 0 never written (stays zero).
// ---------------------------------------------------------------------------
__global__ __launch_bounds__(256) void k2_tilescan(const float4* __restrict__ S4,
                                                   float4* __restrict__ off4) {
    const int g   = blockIdx.x * 256 + threadIdx.x;   // 0 .. B*8192-1
    const int b   = g >> 13;
    const int rem = g & 8191;
    const float4* Sb = S4 + (size_t)b * (H_ * W_ * C_ / 4);
    float4* Ob = off4 + (size_t)b * (NT_ * W_ * C_ / 4);

    float4 acc = Sb[(size_t)3 * 8192 + rem];
    #pragma unroll
    for (int t = 1; t < NT_; t++) {
        Ob[(size_t)t * 8192 + rem] = acc;
        if (t < NT_ - 1) {
            const float4 v = Sb[(size_t)(t * YT_ + 3) * 8192 + rem];
            acc.x += v.x; acc.y += v.y; acc.z += v.z; acc.w += v.w;
        }
    }
}

// ---------------------------------------------------------------------------
// K3: gather (R8 predicated form). Grid = (B*Q, 4 cgroups of 64 ch).
// 256 thr = 16 ch-quads x 16 bin stripes; 3 bins/thread straight-line.
// Output stores streamed (__stcs): never re-read, keep SAT in L2.
// ---------------------------------------------------------------------------
__global__ __launch_bounds__(256) void k3_gather(const int* __restrict__ rois,
                                                 const float* __restrict__ S,
                                                 const float* __restrict__ off,
                                                 float* __restrict__ out) {
    const int bq = blockIdx.x;           // 0 .. B*Q-1
    const int cg = blockIdx.y;           // 0..3 (64 channels)
    const int b  = bq / Q_;
    const int tid = threadIdx.x;

    __shared__ int   e_ys[OUT_], e_ye[OUT_], e_xs[OUT_], e_xe[OUT_];
    __shared__ float ia[BINS];
    __shared__ float stage[64 * 51];

    const int* r = rois + bq * 5;        // [bidx, x1, y1, x2, y2]

    if (tid < OUT_) {
        int y1 = r[2], leny = r[4] - r[2];
        e_ys[tid] = y1 + (tid * leny) / OUT_;
        e_ye[tid] = y1 + ((tid + 1) * leny + (OUT_ - 1)) / OUT_;
    } else if (tid < 2 * OUT_) {
        int k = tid - OUT_;
        int x1 = r[1], lenx = r[3] - r[1];
        e_xs[k] = x1 + (k * lenx) / OUT_;
        e_xe[k] = x1 + ((k + 1) * lenx + (OUT_ - 1)) / OUT_;
    }
    __syncthreads();
    if (tid < BINS) {
        int oy = tid / OUT_, ox = tid % OUT_;
        ia[tid] = 1.0f / (float)((e_ye[oy] - e_ys[oy]) * (e_xe[ox] - e_xs[ox]));
    }
    __syncthreads();

    const int lane16 = tid & 15;
    const int sub    = tid >> 4;         // 0..15
    const int c4     = cg * 16 + lane16;

    const float4* Sb4 = reinterpret_cast<const float4*>(S)
                      + (size_t)b * (H_ * W_ * C_ / 4);
    const float4* Ob4 = reinterpret_cast<const float4*>(off)
                      + (size_t)b * (NT_ * W_ * C_ / 4);

    auto evalbin = [&](int bin) -> float4 {
        const int oy = bin / OUT_, ox = bin % OUT_;
        const int ye = e_ye[oy] - 1, xe = e_xe[ox] - 1;   // always >= 0
        const int ys = e_ys[oy] - 1, xs = e_xs[ox] - 1;   // may be -1
        const bool hy = (ys >= 0), hx = (xs >= 0);
        const int ysc = hy ? ys : 0, xsc = hx ? xs : 0;
        const int tye = ye >> 2, tys = ysc >> 2;

        float4 a = Sb4[((size_t)ye * W_ + xe) * 64 + c4];
        float4 t;
        t = Sb4[((size_t)ysc * W_ + xe) * 64 + c4];
        if (hy) { a.x -= t.x; a.y -= t.y; a.z -= t.z; a.w -= t.w; }
        t = Sb4[((size_t)ye * W_ + xsc) * 64 + c4];
        if (hx) { a.x -= t.x; a.y -= t.y; a.z -= t.z; a.w -= t.w; }
        t = Sb4[((size_t)ysc * W_ + xsc) * 64 + c4];
        if (hy && hx) { a.x += t.x; a.y += t.y; a.z += t.z; a.w += t.w; }

        t = Ob4[((size_t)tye * W_ + xe) * 64 + c4];
        a.x += t.x; a.y += t.y; a.z += t.z; a.w += t.w;
        t = Ob4[((size_t)tys * W_ + xe) * 64 + c4];
        if (hy) { a.x -= t.x; a.y -= t.y; a.z -= t.z; a.w -= t.w; }
        t = Ob4[((size_t)tye * W_ + xsc) * 64 + c4];
        if (hx) { a.x -= t.x; a.y -= t.y; a.z -= t.z; a.w -= t.w; }
        t = Ob4[((size_t)tys * W_ + xsc) * 64 + c4];
        if (hy && hx) { a.x += t.x; a.y += t.y; a.z += t.z; a.w += t.w; }

        const float sc = ia[bin];
        return make_float4(a.x * sc, a.y * sc, a.z * sc, a.w * sc);
    };

    auto stput = [&](int bin, float4 v) {
        const int row = lane16 * 4;
        stage[(row + 0) * 51 + bin] = v.x;
        stage[(row + 1) * 51 + bin] = v.y;
        stage[(row + 2) * 51 + bin] = v.z;
        stage[(row + 3) * 51 + bin] = v.w;
    };

    const float4 r0 = evalbin(sub);
    const float4 r1 = evalbin(sub + 16);
    const float4 r2 = evalbin(sub + 32);
    stput(sub,      r0);
    stput(sub + 16, r1);
    stput(sub + 32, r2);
    if (sub == 0) stput(48, evalbin(48));
    __syncthreads();

    // contiguous slab: out[(bq*256 + cg*64 + ch)*49 + bin], 3136 floats
    float* ob = out + ((size_t)bq * C_ + cg * 64) * BINS;
    #pragma unroll
    for (int i = tid; i < 64 * BINS; i += 256) {
        __stcs(ob + i, stage[(i / BINS) * 51 + (i % BINS)]);
    }
}

// ---------------------------------------------------------------------------
extern "C" void kernel_launch(void* const* d_in, const int* in_sizes, int n_in,
                              void* d_out, int out_size) {
    const float* x    = (const float*)d_in[0];
    const int*   rois = (const int*)d_in[1];
    float*       out  = (float*)d_out;

    float *sat, *off;
    cudaGetSymbolAddress((void**)&sat, g_sat);
    cudaGetSymbolAddress((void**)&off, g_off);

    k1_fused<<<B_ * NT_ * 16, 256>>>(x, sat);

    k2_tilescan<<<(B_ * 8192) / 256, 256>>>((const float4*)sat, (float4*)off);

    dim3 g3(B_ * Q_, 4);
    k3_gather<<<g3, 256>>>(rois, sat, off, out);
}